// round 10
// baseline (speedup 1.0000x reference)
#include <cuda_runtime.h>
#include <math.h>

#define NN 50000
#define NE 800000
#define L  64
#define NB32 ((NN + 31) / 32)
#define NB64 ((NN + 63) / 64)

// ------------- device scratch (statics zero-initialized; k_fin re-zeroes) -------------
__device__ float  g_H [NN*L];
__device__ float  g_H0[NN*L];
__device__ float  g_Pt[NN*L];
__device__ float  g_Qt[NN*L];
__device__ float  g_Pf[NN*L];
__device__ float  g_Qf[NN*L];
__device__ float  g_mt[NN*L];
__device__ float  g_mf[NN*L];
__device__ float  g_U [NN];
__device__ int    g_rowptr[NN+1];
__device__ int    g_colptr[NN+1];
__device__ int    g_cntr[NN];
__device__ int    g_cntc[NN];
__device__ int    g_nd[NN];
__device__ int    g_dr[NN];
__device__ int    g_ndcount;
__device__ int    g_drcount;
__device__ float4 g_rowE4[NE];
__device__ float4 g_colE4[NE];
__device__ float  g_rowA[NE];
__device__ int    g_rowJ[NE];
__device__ double g_loss;

__device__ __forceinline__ float sigf(float v){ return 1.f/(1.f+__expf(-v)); }

// ---------------- CSR build ----------------
__global__ void k_hist(const int* __restrict__ ei){
    int e = blockIdx.x*blockDim.x + threadIdx.x;
    if(e < NE){
        atomicAdd(&g_cntr[ei[e]], 1);
        atomicAdd(&g_cntc[ei[NE+e]], 1);
    }
}

__device__ void scan_one(int* cnt, int* ptr, int* part){
    const int C = (NN + 1023)/1024;
    int t = threadIdx.x;
    int s = 0;
    for(int k=0;k<C;k++){ int id=t*C+k; if(id<NN) s += cnt[id]; }
    part[t] = s; __syncthreads();
    for(int off=1; off<1024; off<<=1){
        int v = (t>=off)? part[t-off] : 0;
        __syncthreads();
        part[t] += v;
        __syncthreads();
    }
    int run = (t==0)? 0 : part[t-1];
    for(int k=0;k<C;k++){
        int id = t*C+k;
        if(id<NN){ int v=cnt[id]; ptr[id]=run; run+=v; cnt[id]=0; }
    }
    if(t==0) ptr[NN] = part[1023];
    __syncthreads();
}

__global__ void k_scan(const int* __restrict__ tags){
    __shared__ int part[1024];
    scan_one(g_cntr, g_rowptr, part);
    scan_one(g_cntc, g_colptr, part);
    const int C = (NN + 1023)/1024;
    int t = threadIdx.x;
    int cN = 0;
    for(int k=0;k<C;k++){ int id=t*C+k; if(id<NN && tags[id]!=1) cN++; }
    part[t] = cN; __syncthreads();
    for(int off=1; off<1024; off<<=1){
        int v = (t>=off)? part[t-off] : 0;
        __syncthreads();
        part[t] += v;
        __syncthreads();
    }
    int ndBase = (t==0)? 0 : part[t-1];
    int idsBefore = t*C; if(idsBefore > NN) idsBefore = NN;
    int drBase = idsBefore - ndBase;
    for(int k=0;k<C;k++){
        int id = t*C+k;
        if(id<NN){
            if(tags[id]!=1) g_nd[ndBase++] = id;
            else            g_dr[drBase++] = id;
        }
    }
    if(t==1023){ g_ndcount = part[1023]; g_drcount = NN - part[1023]; }
}

__global__ void k_scatter(const int* __restrict__ ei, const float* __restrict__ ea,
                          const float* __restrict__ aij){
    int e = blockIdx.x*blockDim.x + threadIdx.x;
    if(e >= NE) return;
    int r = ei[e], c = ei[NE+e];
    float a0 = ea[3*e], a1 = ea[3*e+1], a2 = ea[3*e+2];
    int pr = atomicAdd(&g_cntr[r], 1);
    int p  = g_rowptr[r] + pr;
    g_rowE4[p] = make_float4(a0,a1,a2,__int_as_float(c));
    g_rowA[p]  = aij[e];
    g_rowJ[p]  = c;
    int pc = atomicAdd(&g_cntc[c], 1);
    int q  = g_colptr[c] + pc;
    g_colE4[q] = make_float4(a0,a1,a2,__int_as_float(r));
}

// ---------------- encoder: x -> H0, H ----------------
__global__ __launch_bounds__(256) void k_enc0(const float* __restrict__ x,
        const float* __restrict__ eW1, const float* __restrict__ eb1,
        const float* __restrict__ eW2, const float* __restrict__ eb2){
    __shared__ float sW[L*L];
    __shared__ float sh[8][4][L];
    int tid = threadIdx.x;
    for(int i=tid;i<L*L/4;i+=256) ((float4*)sW)[i] = ((const float4*)eW2)[i];
    __syncthreads();
    int lane = tid&31, w = tid>>5, c0 = 2*lane;
    int nb = blockIdx.x*32 + w*4;
    float w1a=eW1[c0], w1b=eW1[c0+1], b1a=eb1[c0], b1b=eb1[c0+1];
    float b2a=eb2[c0], b2b=eb2[c0+1];
    bool val[4];
    #pragma unroll
    for(int v=0;v<4;v++){
        int n = nb+v; val[v] = (n<NN);
        float xv = val[v]? x[n] : 0.f;
        sh[w][v][c0]   = fmaxf(fmaf(xv,w1a,b1a),0.f);
        sh[w][v][c0+1] = fmaxf(fmaf(xv,w1b,b1b),0.f);
    }
    __syncwarp();
    float a0[4]={b2a,b2a,b2a,b2a}, a1[4]={b2b,b2b,b2b,b2b};
    for(int k=0;k<L;k++){
        float2 wv = *(const float2*)&sW[k*L+c0];
        #pragma unroll
        for(int v=0;v<4;v++){ float s=sh[w][v][k]; a0[v]=fmaf(s,wv.x,a0[v]); a1[v]=fmaf(s,wv.y,a1[v]); }
    }
    #pragma unroll
    for(int v=0;v<4;v++) if(val[v]){
        int n = nb+v;
        g_H0[n*L+c0]=a0[v]; g_H0[n*L+c0+1]=a1[v];
        g_H [n*L+c0]=a0[v]; g_H [n*L+c0+1]=a1[v];
    }
}

// ---------------- P/Q precompute (both phis), 8 nodes/warp, optional nd-perm ----------------
#define PREP_SMEM ((4*L*L + 64*L)*4)
__global__ __launch_bounds__(256) void k_prep(
        const float* __restrict__ ptW1, const float* __restrict__ ptb1,
        const float* __restrict__ pfW1, const float* __restrict__ pfb1,
        int use_perm){
    if(use_perm && blockIdx.x*64 >= g_ndcount) return;
    extern __shared__ float sm[];
    float* Wat = sm;
    float* Wbt = sm + L*L;
    float* Waf = sm + 2*L*L;
    float* Wbf = sm + 3*L*L;
    float* stg = sm + 4*L*L;
    int tid = threadIdx.x;
    for(int i=tid;i<L*L/4;i+=256){
        ((float4*)Wat)[i] = ((const float4*)ptW1)[i];
        ((float4*)Wbt)[i] = ((const float4*)(ptW1+L*L))[i];
        ((float4*)Waf)[i] = ((const float4*)pfW1)[i];
        ((float4*)Wbf)[i] = ((const float4*)(pfW1+L*L))[i];
    }
    int lane = tid&31, w = tid>>5, c0 = 2*lane;
    int i0 = w*8, sb = blockIdx.x*64 + i0;
    int nid[8]; bool val[8];
    #pragma unroll
    for(int v=0;v<8;v++){
        int slot = sb+v;
        if(use_perm){ val[v] = (slot < g_ndcount); nid[v] = val[v]? g_nd[slot] : 0; }
        else        { val[v] = (slot < NN);        nid[v] = slot; }
        float2 h = val[v]? *(const float2*)&g_H[nid[v]*L+c0] : make_float2(0.f,0.f);
        *(float2*)&stg[(i0+v)*L+c0] = h;
    }
    __syncthreads();
    float pt0[8],pt1[8],qt0[8],qt1[8],pf0[8],pf1[8],qf0[8],qf1[8];
    float bt0=ptb1[c0], bt1=ptb1[c0+1], bf0=pfb1[c0], bf1=pfb1[c0+1];
    #pragma unroll
    for(int v=0;v<8;v++){ pt0[v]=bt0; pt1[v]=bt1; pf0[v]=bf0; pf1[v]=bf1;
                          qt0[v]=0.f; qt1[v]=0.f; qf0[v]=0.f; qf1[v]=0.f; }
    for(int k=0;k<L;k++){
        float2 wat = *(const float2*)&Wat[k*L+c0];
        float2 wbt = *(const float2*)&Wbt[k*L+c0];
        float2 waf = *(const float2*)&Waf[k*L+c0];
        float2 wbf = *(const float2*)&Wbf[k*L+c0];
        #pragma unroll
        for(int v=0;v<8;v++){
            float h = stg[(i0+v)*L + k];
            pt0[v]=fmaf(h,wat.x,pt0[v]); pt1[v]=fmaf(h,wat.y,pt1[v]);
            qt0[v]=fmaf(h,wbt.x,qt0[v]); qt1[v]=fmaf(h,wbt.y,qt1[v]);
            pf0[v]=fmaf(h,waf.x,pf0[v]); pf1[v]=fmaf(h,waf.y,pf1[v]);
            qf0[v]=fmaf(h,wbf.x,qf0[v]); qf1[v]=fmaf(h,wbf.y,qf1[v]);
        }
    }
    #pragma unroll
    for(int v=0;v<8;v++) if(val[v]){
        int n = nid[v];
        g_Pt[n*L+c0]=pt0[v]; g_Pt[n*L+c0+1]=pt1[v];
        g_Qt[n*L+c0]=qt0[v]; g_Qt[n*L+c0+1]=qt1[v];
        g_Pf[n*L+c0]=pf0[v]; g_Pf[n*L+c0+1]=pf1[v];
        g_Qf[n*L+c0]=qf0[v]; g_Qf[n*L+c0+1]=qf1[v];
    }
}

// ---------------- edge aggregation + W2 fold: joint cursors for MLP ----------------
__global__ __launch_bounds__(256) void k_aggr(
        const int* __restrict__ colptr, const float4* __restrict__ colE4,
        const int* __restrict__ rowptr, const float4* __restrict__ rowE4,
        const float* __restrict__ Pt, const float* __restrict__ Qt,
        const float* __restrict__ Pf, const float* __restrict__ Qf,
        const float* __restrict__ ptW1, const float* __restrict__ ptb2, const float* __restrict__ ptW2,
        const float* __restrict__ pfW1, const float* __restrict__ pfb2, const float* __restrict__ pfW2,
        float* __restrict__ mt, float* __restrict__ mf){
    bool toDir = (blockIdx.x < NB32);
    int bb = toDir ? blockIdx.x : blockIdx.x - NB32;
    if(bb*32 >= g_ndcount) return;
    __shared__ float sW2[L*L];
    __shared__ float sWe[3*L];
    __shared__ float sS[8][4][L];
    const int*    ptr = toDir ? colptr : rowptr;
    const float4* e4  = toDir ? colE4  : rowE4;
    const float*  P   = toDir ? Pt     : Pf;
    const float*  Q   = toDir ? Qt     : Qf;
    const float*  W1  = toDir ? ptW1   : pfW1;
    const float*  b2  = toDir ? ptb2   : pfb2;
    const float*  W2  = toDir ? ptW2   : pfW2;
    float*        out = toDir ? mt     : mf;
    int tid = threadIdx.x;
    for(int i=tid;i<L*L/4;i+=256) ((float4*)sW2)[i] = ((const float4*)W2)[i];
    for(int i=tid;i<3*L;i+=256) sWe[i] = W1[2*L*L + i];
    __syncthreads();
    int lane = tid&31, w = tid>>5, c0 = 2*lane;
    int sb = bb*32 + w*4;
    float we0a=sWe[c0],     we0b=sWe[c0+1];
    float we1a=sWe[L+c0],   we1b=sWe[L+c0+1];
    float we2a=sWe[2*L+c0], we2b=sWe[2*L+c0+1];
    int nid[4]; bool val[4]; int base[4], len[4];
    float b0v[4], b1v[4];
    #pragma unroll
    for(int v=0;v<4;v++){
        int slot = sb+v;
        val[v] = (slot < g_ndcount);
        int n = val[v]? g_nd[slot] : 0;
        nid[v] = n;
        base[v] = val[v]? ptr[n] : 0;
        len[v]  = val[v]? (ptr[n+1] - base[v]) : 0;
        b0v[v] = val[v]? P[n*L+c0]   : 0.f;
        b1v[v] = val[v]? P[n*L+c0+1] : 0.f;
    }
    int maxlen = max(max(len[0],len[1]), max(len[2],len[3]));
    float acc0[4]={0,0,0,0}, acc1[4]={0,0,0,0}, cntf[4]={0,0,0,0};
    for(int it=0; it<maxlen; it++){
        float4 E[4]; bool act[4];
        #pragma unroll
        for(int v=0;v<4;v++){
            act[v] = (it < len[v]);
            E[v] = act[v]? e4[base[v]+it]
                         : make_float4(0.f,0.f,0.f,__int_as_float(nid[v]));
        }
        int jj[4]; float2 qv[4];
        #pragma unroll
        for(int v=0;v<4;v++){
            jj[v] = __float_as_int(E[v].w);
            qv[v] = act[v]? *(const float2*)&Q[jj[v]*L+c0] : make_float2(0.f,0.f);
        }
        #pragma unroll
        for(int v=0;v<4;v++){
            bool keep = act[v] && (jj[v] != nid[v]);
            float pre0 = b0v[v] + qv[v].x + E[v].x*we0a + E[v].y*we1a + E[v].z*we2a;
            float pre1 = b1v[v] + qv[v].y + E[v].x*we0b + E[v].y*we1b + E[v].z*we2b;
            if(keep){
                acc0[v] += fmaxf(pre0, 0.f);
                acc1[v] += fmaxf(pre1, 0.f);
                cntf[v] += 1.f;
            }
        }
    }
    #pragma unroll
    for(int v=0;v<4;v++){ sS[w][v][c0]=acc0[v]; sS[w][v][c0+1]=acc1[v]; }
    __syncwarp();
    float b2a=b2[c0], b2b=b2[c0+1];
    float o0[4],o1[4];
    #pragma unroll
    for(int v=0;v<4;v++){ o0[v]=cntf[v]*b2a; o1[v]=cntf[v]*b2b; }
    for(int k=0;k<L;k++){
        float2 wv = *(const float2*)&sW2[k*L+c0];
        #pragma unroll
        for(int v=0;v<4;v++){ float s=sS[w][v][k]; o0[v]=fmaf(s,wv.x,o0[v]); o1[v]=fmaf(s,wv.y,o1[v]); }
    }
    #pragma unroll
    for(int v=0;v<4;v++) if(val[v]){
        int n = nid[v];
        out[n*L+c0]=o0[v]; out[n*L+c0+1]=o1[v];
    }
}

// ---------------- fused gates + decode + losses (non-dir nodes) ----------------
#define GATE_SMEM ((3*194*L + 64*196 + 64*L)*4)
__global__ __launch_bounds__(256) void k_gatedec(
        const float* __restrict__ prb,
        const float* __restrict__ zkW, const float* __restrict__ zkb,
        const float* __restrict__ rkW, const float* __restrict__ rkb,
        const float* __restrict__ cW,  const float* __restrict__ cb,
        const float* __restrict__ dW1, const float* __restrict__ db1,
        const float* __restrict__ dW2, const float* __restrict__ db2,
        const float* __restrict__ eW1, const float* __restrict__ eb1,
        const float* __restrict__ eW2, const float* __restrict__ eb2){
    if(blockIdx.x*64 >= g_ndcount) return;
    extern __shared__ float sm[];
    float* szk  = sm;
    float* srk  = szk + 194*L;
    float* scw  = srk + 194*L;
    float* stgA = scw + 194*L;        // [64][196]
    float* stgB = stgA + 64*196;      // [64][64]
    __shared__ float szb[L], srb[L], scb[L];
    __shared__ float sdW2[L], sdb1[L], sE1[L], sEb1[L], sEb2[L];
    __shared__ double red[8];
    int tid = threadIdx.x;
    for(int i=tid;i<194*L/4;i+=256){
        ((float4*)szk)[i] = ((const float4*)zkW)[i];
        ((float4*)srk)[i] = ((const float4*)rkW)[i];
        ((float4*)scw)[i] = ((const float4*)cW)[i];
    }
    if(tid<L){ szb[tid]=zkb[tid]; srb[tid]=rkb[tid]; scb[tid]=cb[tid];
               sdW2[tid]=dW2[tid]; sdb1[tid]=db1[tid]; sE1[tid]=eW1[tid];
               sEb1[tid]=eb1[tid]; sEb2[tid]=eb2[tid]; }
    int lane = tid&31, w = tid>>5, c0 = 2*lane;
    int i0 = w*8, sb = blockIdx.x*64 + i0;
    float db2v = db2[0];
    int nid[8]; bool val[8];
    #pragma unroll
    for(int v=0;v<8;v++){
        int slot = sb+v; val[v] = (slot < g_ndcount);
        int n = val[v]? g_nd[slot] : 0; nid[v] = n;
        float* A = stgA + (i0+v)*196;
        if(val[v]){
            *(float2*)&A[c0]     = *(const float2*)&g_H [n*L+c0];
            *(float2*)&A[64+c0]  = *(const float2*)&g_mt[n*L+c0];
            *(float2*)&A[128+c0] = *(const float2*)&g_mf[n*L+c0];
            if(lane==0){ A[192]=prb[2*n]; A[193]=prb[2*n+1]; }
        } else {
            *(float2*)&A[c0]     = make_float2(0.f,0.f);
            *(float2*)&A[64+c0]  = make_float2(0.f,0.f);
            *(float2*)&A[128+c0] = make_float2(0.f,0.f);
            if(lane==0){ A[192]=0.f; A[193]=0.f; }
        }
    }
    __syncthreads();
    float az0[8],az1[8],ar0[8],ar1[8],ac0[8],ac1[8];
    #pragma unroll
    for(int v=0;v<8;v++){ az0[v]=0.f; az1[v]=0.f; ar0[v]=0.f; ar1[v]=0.f; ac0[v]=0.f; ac1[v]=0.f; }
    for(int k=0;k<64;k++){
        float2 wz = *(const float2*)&szk[k*L+c0];
        float2 wr = *(const float2*)&srk[k*L+c0];
        #pragma unroll
        for(int v=0;v<8;v++){
            float cv = stgA[(i0+v)*196 + k];
            az0[v]=fmaf(cv,wz.x,az0[v]); az1[v]=fmaf(cv,wz.y,az1[v]);
            ar0[v]=fmaf(cv,wr.x,ar0[v]); ar1[v]=fmaf(cv,wr.y,ar1[v]);
        }
    }
    for(int k=64;k<194;k++){
        float2 wz = *(const float2*)&szk[k*L+c0];
        float2 wr = *(const float2*)&srk[k*L+c0];
        float2 wc = *(const float2*)&scw[k*L+c0];
        #pragma unroll
        for(int v=0;v<8;v++){
            float cv = stgA[(i0+v)*196 + k];
            az0[v]=fmaf(cv,wz.x,az0[v]); az1[v]=fmaf(cv,wz.y,az1[v]);
            ar0[v]=fmaf(cv,wr.x,ar0[v]); ar1[v]=fmaf(cv,wr.y,ar1[v]);
            ac0[v]=fmaf(cv,wc.x,ac0[v]); ac1[v]=fmaf(cv,wc.y,ac1[v]);
        }
    }
    float z0[8],z1[8];
    #pragma unroll
    for(int v=0;v<8;v++){
        z0[v]=sigf(az0[v]+szb[c0]); z1[v]=sigf(az1[v]+szb[c0+1]);
        float rr0=sigf(ar0[v]+srb[c0]), rr1=sigf(ar1[v]+srb[c0+1]);
        stgB[(i0+v)*L+c0]=rr0; stgB[(i0+v)*L+c0+1]=rr1;
    }
    __syncwarp();
    for(int k=0;k<64;k++){
        float2 wc = *(const float2*)&scw[k*L+c0];
        #pragma unroll
        for(int v=0;v<8;v++){
            float rh = stgB[(i0+v)*L+k] * stgA[(i0+v)*196+k];
            ac0[v]=fmaf(rh,wc.x,ac0[v]); ac1[v]=fmaf(rh,wc.y,ac1[v]);
        }
    }
    // Hn -> g_H, keep in regs + stgA
    float Hn0[8], Hn1[8];
    #pragma unroll
    for(int v=0;v<8;v++){
        float* A = stgA + (i0+v)*196;
        float co0 = tanhf(ac0[v]+scb[c0]);
        float co1 = tanhf(ac1[v]+scb[c0+1]);
        float hn0 = A[c0]   + z0[v]*co0;
        float hn1 = A[c0+1] + z1[v]*co1;
        Hn0[v]=hn0; Hn1[v]=hn1;
        A[c0]=hn0; A[c0+1]=hn1;
        if(val[v]){ g_H[nid[v]*L+c0]=hn0; g_H[nid[v]*L+c0+1]=hn1; }
    }
    __syncwarp();
    // decoder
    float ad0[8],ad1[8];
    #pragma unroll
    for(int v=0;v<8;v++){ ad0[v]=sdb1[c0]; ad1[v]=sdb1[c0+1]; }
    for(int k=0;k<L;k++){
        float2 wd = __ldg((const float2*)&dW1[k*L+c0]);
        #pragma unroll
        for(int v=0;v<8;v++){
            float hk = stgA[(i0+v)*196 + k];
            ad0[v]=fmaf(hk,wd.x,ad0[v]); ad1[v]=fmaf(hk,wd.y,ad1[v]);
        }
    }
    float Uv[8];
    #pragma unroll
    for(int v=0;v<8;v++){
        float pu = fmaxf(ad0[v],0.f)*sdW2[c0] + fmaxf(ad1[v],0.f)*sdW2[c0+1];
        for(int o=16;o;o>>=1) pu += __shfl_xor_sync(0xffffffffu, pu, o);
        Uv[v] = pu + db2v;
        if(val[v] && lane==0) g_U[nid[v]] = Uv[v];
        float eh0 = fmaxf(fmaf(Uv[v],sE1[c0],sEb1[c0]),0.f);
        float eh1 = fmaxf(fmaf(Uv[v],sE1[c0+1],sEb1[c0+1]),0.f);
        stgB[(i0+v)*L+c0]=eh0; stgB[(i0+v)*L+c0+1]=eh1;
    }
    __syncwarp();
    // enc(U)
    float ae0[8],ae1[8];
    #pragma unroll
    for(int v=0;v<8;v++){ ae0[v]=sEb2[c0]; ae1[v]=sEb2[c0+1]; }
    for(int k=0;k<L;k++){
        float2 we = __ldg((const float2*)&eW2[k*L+c0]);
        #pragma unroll
        for(int v=0;v<8;v++){
            float ek = stgB[(i0+v)*L+k];
            ae0[v]=fmaf(ek,we.x,ae0[v]); ae1[v]=fmaf(ek,we.y,ae1[v]);
        }
    }
    float encS = 0.f;
    #pragma unroll
    for(int v=0;v<8;v++){
        float* A = stgA + (i0+v)*196;
        if(val[v]){
            float d0 = ae0[v]-Hn0[v], d1 = ae1[v]-Hn1[v];
            encS += d0*d0 + d1*d1;
        }
        A[64+c0]=ae0[v]; A[64+c0+1]=ae1[v];
    }
    __syncwarp();
    // autoenc: dec(enc)
    float ag0[8],ag1[8];
    #pragma unroll
    for(int v=0;v<8;v++){ ag0[v]=sdb1[c0]; ag1[v]=sdb1[c0+1]; }
    for(int k=0;k<L;k++){
        float2 wd = __ldg((const float2*)&dW1[k*L+c0]);
        #pragma unroll
        for(int v=0;v<8;v++){
            float ek = stgA[(i0+v)*196 + 64 + k];
            ag0[v]=fmaf(ek,wd.x,ag0[v]); ag1[v]=fmaf(ek,wd.y,ag1[v]);
        }
    }
    float autoS = 0.f;
    #pragma unroll
    for(int v=0;v<8;v++){
        float pa = fmaxf(ag0[v],0.f)*sdW2[c0] + fmaxf(ag1[v],0.f)*sdW2[c0+1];
        for(int o=16;o;o>>=1) pa += __shfl_xor_sync(0xffffffffu, pa, o);
        float aout = pa + db2v;
        if(val[v] && lane==0){ float d = aout - Uv[v]; autoS += d*d; }
    }
    float tot = encS;
    for(int o=16;o;o>>=1) tot += __shfl_xor_sync(0xffffffffu, tot, o);
    float at = autoS;
    for(int o=16;o;o>>=1) at += __shfl_xor_sync(0xffffffffu, at, o);
    if(lane==0) red[w] = (double)tot/((double)NN*64.0) + (double)at/(double)NN;
    __syncthreads();
    if(tid==0){
        double s = 0.0;
        for(int i=0;i<8;i++) s += red[i];
        atomicAdd(&g_loss, s);
    }
}

// ---------------- decode + losses over Dirichlet list (once, weight 2) ----------------
#define DEC_SMEM (3*64*L*4)
__global__ __launch_bounds__(256) void k_decode(
        float lossW,
        const float* __restrict__ dW1, const float* __restrict__ db1,
        const float* __restrict__ dW2, const float* __restrict__ db2,
        const float* __restrict__ eW1, const float* __restrict__ eb1,
        const float* __restrict__ eW2, const float* __restrict__ eb2){
    int cnt = g_drcount;
    if(blockIdx.x*64 >= cnt) return;
    const int* list = g_dr;
    extern __shared__ float sm[];
    float* sHn = sm;
    float* sB  = sm + 64*L;
    float* sE  = sm + 2*64*L;
    __shared__ float sdW2[L], sdb1[L], sE1[L], sEb1[L], sEb2[L];
    __shared__ double red[8];
    int tid = threadIdx.x;
    if(tid<L){ sdW2[tid]=dW2[tid]; sdb1[tid]=db1[tid]; sE1[tid]=eW1[tid];
               sEb1[tid]=eb1[tid]; sEb2[tid]=eb2[tid]; }
    __syncthreads();
    int lane = tid&31, w = tid>>5, c0 = 2*lane;
    int i0 = w*8, sb = blockIdx.x*64 + i0;
    float db2v = db2[0];
    int nid[8]; bool val[8];
    #pragma unroll
    for(int v=0;v<8;v++){
        int slot = sb+v; val[v] = (slot < cnt);
        nid[v] = val[v]? list[slot] : 0;
        float2 h = val[v]? *(const float2*)&g_H[nid[v]*L+c0] : make_float2(0.f,0.f);
        *(float2*)&sHn[(i0+v)*L+c0] = h;
    }
    __syncwarp();
    float ad0[8],ad1[8];
    #pragma unroll
    for(int v=0;v<8;v++){ ad0[v]=sdb1[c0]; ad1[v]=sdb1[c0+1]; }
    for(int k=0;k<L;k++){
        float2 wd = __ldg((const float2*)&dW1[k*L+c0]);
        #pragma unroll
        for(int v=0;v<8;v++){
            float hk = sHn[(i0+v)*L+k];
            ad0[v]=fmaf(hk,wd.x,ad0[v]); ad1[v]=fmaf(hk,wd.y,ad1[v]);
        }
    }
    float Uv[8];
    #pragma unroll
    for(int v=0;v<8;v++){
        float pu = fmaxf(ad0[v],0.f)*sdW2[c0] + fmaxf(ad1[v],0.f)*sdW2[c0+1];
        for(int o=16;o;o>>=1) pu += __shfl_xor_sync(0xffffffffu, pu, o);
        Uv[v] = pu + db2v;
        if(val[v] && lane==0) g_U[nid[v]] = Uv[v];
        float eh0 = fmaxf(fmaf(Uv[v],sE1[c0],sEb1[c0]),0.f);
        float eh1 = fmaxf(fmaf(Uv[v],sE1[c0+1],sEb1[c0+1]),0.f);
        sB[(i0+v)*L+c0]=eh0; sB[(i0+v)*L+c0+1]=eh1;
    }
    __syncwarp();
    float ae0[8],ae1[8];
    #pragma unroll
    for(int v=0;v<8;v++){ ae0[v]=sEb2[c0]; ae1[v]=sEb2[c0+1]; }
    for(int k=0;k<L;k++){
        float2 we = __ldg((const float2*)&eW2[k*L+c0]);
        #pragma unroll
        for(int v=0;v<8;v++){
            float ek = sB[(i0+v)*L+k];
            ae0[v]=fmaf(ek,we.x,ae0[v]); ae1[v]=fmaf(ek,we.y,ae1[v]);
        }
    }
    float encS = 0.f;
    #pragma unroll
    for(int v=0;v<8;v++){
        if(val[v]){
            float d0 = ae0[v]-sHn[(i0+v)*L+c0], d1 = ae1[v]-sHn[(i0+v)*L+c0+1];
            encS += d0*d0 + d1*d1;
        }
        sE[(i0+v)*L+c0]=ae0[v]; sE[(i0+v)*L+c0+1]=ae1[v];
    }
    __syncwarp();
    float ag0[8],ag1[8];
    #pragma unroll
    for(int v=0;v<8;v++){ ag0[v]=sdb1[c0]; ag1[v]=sdb1[c0+1]; }
    for(int k=0;k<L;k++){
        float2 wd = __ldg((const float2*)&dW1[k*L+c0]);
        #pragma unroll
        for(int v=0;v<8;v++){
            float ek = sE[(i0+v)*L+k];
            ag0[v]=fmaf(ek,wd.x,ag0[v]); ag1[v]=fmaf(ek,wd.y,ag1[v]);
        }
    }
    float autoS = 0.f;
    #pragma unroll
    for(int v=0;v<8;v++){
        float pa = fmaxf(ag0[v],0.f)*sdW2[c0] + fmaxf(ag1[v],0.f)*sdW2[c0+1];
        for(int o=16;o;o>>=1) pa += __shfl_xor_sync(0xffffffffu, pa, o);
        float aout = pa + db2v;
        if(val[v] && lane==0){ float d = aout - Uv[v]; autoS += d*d; }
    }
    float tot = encS;
    for(int o=16;o;o>>=1) tot += __shfl_xor_sync(0xffffffffu, tot, o);
    float at = autoS;
    for(int o=16;o;o>>=1) at += __shfl_xor_sync(0xffffffffu, at, o);
    if(lane==0) red[w] = (double)lossW * ((double)tot/((double)NN*64.0) + (double)at/(double)NN);
    __syncthreads();
    if(tid==0){
        double s = 0.0;
        for(int i=0;i<8;i++) s += red[i];
        atomicAdd(&g_loss, s);
    }
}

// ---------------- residual loss (rowJ/rowA: 8B/edge) ----------------
__global__ __launch_bounds__(256) void k_res(const float* __restrict__ y, float wgt){
    __shared__ double red[8];
    int lane = threadIdx.x&31, w = threadIdx.x>>5;
    int wid = blockIdx.x*8 + w;
    int nwarps = gridDim.x*8;
    float ls = 0.f;
    for(int n = wid; n < NN; n += nwarps){
        int s = g_rowptr[n], e = g_rowptr[n+1];
        float part = 0.f;
        for(int p = s+lane; p < e; p += 32){
            part += g_rowA[p] * g_U[g_rowJ[p]];
        }
        for(int o=16;o;o>>=1) part += __shfl_xor_sync(0xffffffffu, part, o);
        if(lane==0){ float d = part - y[n]; ls += d*d; }
    }
    for(int o=16;o;o>>=1) ls += __shfl_xor_sync(0xffffffffu, ls, o);
    if(lane==0) red[w] = (double)ls;
    __syncthreads();
    if(threadIdx.x==0){
        double s=0.0; for(int i=0;i<8;i++) s+=red[i];
        atomicAdd(&g_loss, s * (double)wgt / (double)NN);
    }
}

// ---------------- finalize + reset state for next replay ----------------
__global__ void k_fin(float* __restrict__ out, int out_size){
    int i = blockIdx.x*blockDim.x + threadIdx.x;
    if(i < NN && i < out_size) out[i] = g_U[i];
    if(i == NN){
        if(i < out_size) out[NN] = (float)g_loss;
        g_loss = 0.0;
    }
    if(i < NN){ g_cntr[i]=0; g_cntc[i]=0; }
}

extern "C" void kernel_launch(void* const* d_in, const int* in_sizes, int n_in,
                              void* d_out, int out_size){
    const float* x    = (const float*)d_in[0];
    const float* y    = (const float*)d_in[2];
    const int*   tags = (const int*)  d_in[3];
    const int*   ei   = (const int*)  d_in[4];
    const float* ea   = (const float*)d_in[5];
    const float* aij  = (const float*)d_in[6];
    const float* prb  = (const float*)d_in[7];
    const float* ptW1 = (const float*)d_in[8];
    const float* ptb1 = (const float*)d_in[9];
    const float* ptW2 = (const float*)d_in[10];
    const float* ptb2 = (const float*)d_in[11];
    const float* pfW1 = (const float*)d_in[12];
    const float* pfb1 = (const float*)d_in[13];
    const float* pfW2 = (const float*)d_in[14];
    const float* pfb2 = (const float*)d_in[15];
    const float* zkW  = (const float*)d_in[16];
    const float* zkb  = (const float*)d_in[17];
    const float* rkW  = (const float*)d_in[18];
    const float* rkb  = (const float*)d_in[19];
    const float* cW   = (const float*)d_in[20];
    const float* cb   = (const float*)d_in[21];
    const float* eW1  = (const float*)d_in[22];
    const float* eb1  = (const float*)d_in[23];
    const float* eW2  = (const float*)d_in[24];
    const float* eb2  = (const float*)d_in[25];
    const float* dW1  = (const float*)d_in[26];
    const float* db1  = (const float*)d_in[27];
    const float* dW2  = (const float*)d_in[28];
    const float* db2  = (const float*)d_in[29];

    cudaFuncSetAttribute(k_prep,    cudaFuncAttributeMaxDynamicSharedMemorySize, PREP_SMEM);
    cudaFuncSetAttribute(k_gatedec, cudaFuncAttributeMaxDynamicSharedMemorySize, GATE_SMEM);
    cudaFuncSetAttribute(k_decode,  cudaFuncAttributeMaxDynamicSharedMemorySize, DEC_SMEM);

    int *rowptr, *colptr;
    float4 *rowE4, *colE4;
    float *Pt, *Qt, *Pf, *Qf, *mt, *mf;
    cudaGetSymbolAddress((void**)&rowptr, g_rowptr);
    cudaGetSymbolAddress((void**)&colptr, g_colptr);
    cudaGetSymbolAddress((void**)&rowE4,  g_rowE4);
    cudaGetSymbolAddress((void**)&colE4,  g_colE4);
    cudaGetSymbolAddress((void**)&Pt, g_Pt);
    cudaGetSymbolAddress((void**)&Qt, g_Qt);
    cudaGetSymbolAddress((void**)&Pf, g_Pf);
    cudaGetSymbolAddress((void**)&Qf, g_Qf);
    cudaGetSymbolAddress((void**)&mt, g_mt);
    cudaGetSymbolAddress((void**)&mf, g_mf);

    k_enc0<<<NB32, 256>>>(x, eW1, eb1, eW2, eb2);                        // 0
    k_hist<<<(NE+255)/256, 256>>>(ei);                                   // 1
    k_scan<<<1, 1024>>>(tags);                                           // 2
    k_prep<<<NB64, 256, PREP_SMEM>>>(ptW1, ptb1, pfW1, pfb1, 0);         // 3 (profiled control)
    k_scatter<<<(NE+255)/256, 256>>>(ei, ea, aij);                       // 4
    k_decode<<<NB64, 256, DEC_SMEM>>>(2.0f, dW1, db1, dW2, db2, eW1, eb1, eW2, eb2);

    const float gammaw[2] = {0.9f, 1.0f};
    for(int step=0; step<2; step++){
        k_aggr<<<2*NB32, 256>>>(colptr, colE4, rowptr, rowE4,
                                Pt, Qt, Pf, Qf,
                                ptW1, ptb2, ptW2, pfW1, pfb2, pfW2, mt, mf);
        k_gatedec<<<NB64, 256, GATE_SMEM>>>(prb, zkW, zkb, rkW, rkb, cW, cb,
                                            dW1, db1, dW2, db2, eW1, eb1, eW2, eb2);
        k_res<<<NB32, 256>>>(y, gammaw[step]);
        if(step == 0)
            k_prep<<<NB64, 256, PREP_SMEM>>>(ptW1, ptb1, pfW1, pfb1, 1);
    }
    k_fin<<<(NN+256)/256, 256>>>((float*)d_out, out_size);
}

// round 11
// speedup vs baseline: 1.0734x; 1.0734x over previous
#include <cuda_runtime.h>
#include <math.h>

#define NN 50000
#define NE 800000
#define L  64
#define NB32 ((NN + 31) / 32)
#define NB64 ((NN + 63) / 64)

// ------------- device scratch (statics zero-initialized; k_fin re-zeroes) -------------
__device__ float  g_H [NN*L];
__device__ float  g_H0[NN*L];
__device__ float  g_Pt[NN*L];
__device__ float  g_Qt[NN*L];
__device__ float  g_Pf[NN*L];
__device__ float  g_Qf[NN*L];
__device__ float  g_mt[NN*L];
__device__ float  g_mf[NN*L];
__device__ float  g_U [NN];
__device__ int    g_rowptr[NN+1];
__device__ int    g_colptr[NN+1];
__device__ int    g_cntr[NN];
__device__ int    g_cntc[NN];
__device__ int    g_nd[NN];
__device__ int    g_dr[NN];
__device__ int    g_ndcount;
__device__ int    g_drcount;
__device__ float4 g_rowE4[NE];
__device__ float4 g_colE4[NE];
__device__ float  g_rowA[NE];
__device__ int    g_rowJ[NE];
__device__ double g_loss;

__device__ __forceinline__ float sigf(float v){ return 1.f/(1.f+__expf(-v)); }

// ---------------- CSR build ----------------
__global__ void k_hist(const int* __restrict__ ei){
    int e = blockIdx.x*blockDim.x + threadIdx.x;
    if(e < NE){
        atomicAdd(&g_cntr[ei[e]], 1);
        atomicAdd(&g_cntc[ei[NE+e]], 1);
    }
}

__device__ void scan_one(int* cnt, int* ptr, int* part){
    const int C = (NN + 1023)/1024;
    int t = threadIdx.x;
    int s = 0;
    for(int k=0;k<C;k++){ int id=t*C+k; if(id<NN) s += cnt[id]; }
    part[t] = s; __syncthreads();
    for(int off=1; off<1024; off<<=1){
        int v = (t>=off)? part[t-off] : 0;
        __syncthreads();
        part[t] += v;
        __syncthreads();
    }
    int run = (t==0)? 0 : part[t-1];
    for(int k=0;k<C;k++){
        int id = t*C+k;
        if(id<NN){ int v=cnt[id]; ptr[id]=run; run+=v; cnt[id]=0; }
    }
    if(t==0) ptr[NN] = part[1023];
    __syncthreads();
}

__global__ void k_scan(const int* __restrict__ tags){
    __shared__ int part[1024];
    scan_one(g_cntr, g_rowptr, part);
    scan_one(g_cntc, g_colptr, part);
    const int C = (NN + 1023)/1024;
    int t = threadIdx.x;
    int cN = 0;
    for(int k=0;k<C;k++){ int id=t*C+k; if(id<NN && tags[id]!=1) cN++; }
    part[t] = cN; __syncthreads();
    for(int off=1; off<1024; off<<=1){
        int v = (t>=off)? part[t-off] : 0;
        __syncthreads();
        part[t] += v;
        __syncthreads();
    }
    int ndBase = (t==0)? 0 : part[t-1];
    int idsBefore = t*C; if(idsBefore > NN) idsBefore = NN;
    int drBase = idsBefore - ndBase;
    for(int k=0;k<C;k++){
        int id = t*C+k;
        if(id<NN){
            if(tags[id]!=1) g_nd[ndBase++] = id;
            else            g_dr[drBase++] = id;
        }
    }
    if(t==1023){ g_ndcount = part[1023]; g_drcount = NN - part[1023]; }
}

__global__ void k_scatter(const int* __restrict__ ei, const float* __restrict__ ea,
                          const float* __restrict__ aij){
    int e = blockIdx.x*blockDim.x + threadIdx.x;
    if(e >= NE) return;
    int r = ei[e], c = ei[NE+e];
    float a0 = ea[3*e], a1 = ea[3*e+1], a2 = ea[3*e+2];
    int pr = atomicAdd(&g_cntr[r], 1);
    int p  = g_rowptr[r] + pr;
    g_rowE4[p] = make_float4(a0,a1,a2,__int_as_float(c));
    g_rowA[p]  = aij[e];
    g_rowJ[p]  = c;
    int pc = atomicAdd(&g_cntc[c], 1);
    int q  = g_colptr[c] + pc;
    g_colE4[q] = make_float4(a0,a1,a2,__int_as_float(r));
}

// ---------------- encoder: x -> H0, H ----------------
__global__ __launch_bounds__(256) void k_enc0(const float* __restrict__ x,
        const float* __restrict__ eW1, const float* __restrict__ eb1,
        const float* __restrict__ eW2, const float* __restrict__ eb2){
    __shared__ float sW[L*L];
    __shared__ float sh[8][4][L];
    int tid = threadIdx.x;
    for(int i=tid;i<L*L/4;i+=256) ((float4*)sW)[i] = ((const float4*)eW2)[i];
    __syncthreads();
    int lane = tid&31, w = tid>>5, c0 = 2*lane;
    int nb = blockIdx.x*32 + w*4;
    float w1a=eW1[c0], w1b=eW1[c0+1], b1a=eb1[c0], b1b=eb1[c0+1];
    float b2a=eb2[c0], b2b=eb2[c0+1];
    bool val[4];
    #pragma unroll
    for(int v=0;v<4;v++){
        int n = nb+v; val[v] = (n<NN);
        float xv = val[v]? x[n] : 0.f;
        sh[w][v][c0]   = fmaxf(fmaf(xv,w1a,b1a),0.f);
        sh[w][v][c0+1] = fmaxf(fmaf(xv,w1b,b1b),0.f);
    }
    __syncwarp();
    float a0[4]={b2a,b2a,b2a,b2a}, a1[4]={b2b,b2b,b2b,b2b};
    for(int k=0;k<L;k++){
        float2 wv = *(const float2*)&sW[k*L+c0];
        #pragma unroll
        for(int v=0;v<4;v++){ float s=sh[w][v][k]; a0[v]=fmaf(s,wv.x,a0[v]); a1[v]=fmaf(s,wv.y,a1[v]); }
    }
    #pragma unroll
    for(int v=0;v<4;v++) if(val[v]){
        int n = nb+v;
        g_H0[n*L+c0]=a0[v]; g_H0[n*L+c0+1]=a1[v];
        g_H [n*L+c0]=a0[v]; g_H [n*L+c0+1]=a1[v];
    }
}

// ---------------- P/Q precompute (both phis), 8 nodes/warp, optional nd-perm ----------------
#define PREP_SMEM ((4*L*L + 64*L)*4)
__global__ __launch_bounds__(256) void k_prep(
        const float* __restrict__ ptW1, const float* __restrict__ ptb1,
        const float* __restrict__ pfW1, const float* __restrict__ pfb1,
        int use_perm){
    if(use_perm && blockIdx.x*64 >= g_ndcount) return;
    extern __shared__ float sm[];
    float* Wat = sm;
    float* Wbt = sm + L*L;
    float* Waf = sm + 2*L*L;
    float* Wbf = sm + 3*L*L;
    float* stg = sm + 4*L*L;
    int tid = threadIdx.x;
    for(int i=tid;i<L*L/4;i+=256){
        ((float4*)Wat)[i] = ((const float4*)ptW1)[i];
        ((float4*)Wbt)[i] = ((const float4*)(ptW1+L*L))[i];
        ((float4*)Waf)[i] = ((const float4*)pfW1)[i];
        ((float4*)Wbf)[i] = ((const float4*)(pfW1+L*L))[i];
    }
    int lane = tid&31, w = tid>>5, c0 = 2*lane;
    int i0 = w*8, sb = blockIdx.x*64 + i0;
    int nid[8]; bool val[8];
    #pragma unroll
    for(int v=0;v<8;v++){
        int slot = sb+v;
        if(use_perm){ val[v] = (slot < g_ndcount); nid[v] = val[v]? g_nd[slot] : 0; }
        else        { val[v] = (slot < NN);        nid[v] = slot; }
        float2 h = val[v]? *(const float2*)&g_H[nid[v]*L+c0] : make_float2(0.f,0.f);
        *(float2*)&stg[(i0+v)*L+c0] = h;
    }
    __syncthreads();
    float pt0[8],pt1[8],qt0[8],qt1[8],pf0[8],pf1[8],qf0[8],qf1[8];
    float bt0=ptb1[c0], bt1=ptb1[c0+1], bf0=pfb1[c0], bf1=pfb1[c0+1];
    #pragma unroll
    for(int v=0;v<8;v++){ pt0[v]=bt0; pt1[v]=bt1; pf0[v]=bf0; pf1[v]=bf1;
                          qt0[v]=0.f; qt1[v]=0.f; qf0[v]=0.f; qf1[v]=0.f; }
    for(int k=0;k<L;k++){
        float2 wat = *(const float2*)&Wat[k*L+c0];
        float2 wbt = *(const float2*)&Wbt[k*L+c0];
        float2 waf = *(const float2*)&Waf[k*L+c0];
        float2 wbf = *(const float2*)&Wbf[k*L+c0];
        #pragma unroll
        for(int v=0;v<8;v++){
            float h = stg[(i0+v)*L + k];
            pt0[v]=fmaf(h,wat.x,pt0[v]); pt1[v]=fmaf(h,wat.y,pt1[v]);
            qt0[v]=fmaf(h,wbt.x,qt0[v]); qt1[v]=fmaf(h,wbt.y,qt1[v]);
            pf0[v]=fmaf(h,waf.x,pf0[v]); pf1[v]=fmaf(h,waf.y,pf1[v]);
            qf0[v]=fmaf(h,wbf.x,qf0[v]); qf1[v]=fmaf(h,wbf.y,qf1[v]);
        }
    }
    #pragma unroll
    for(int v=0;v<8;v++) if(val[v]){
        int n = nid[v];
        g_Pt[n*L+c0]=pt0[v]; g_Pt[n*L+c0+1]=pt1[v];
        g_Qt[n*L+c0]=qt0[v]; g_Qt[n*L+c0+1]=qt1[v];
        g_Pf[n*L+c0]=pf0[v]; g_Pf[n*L+c0+1]=pf1[v];
        g_Qf[n*L+c0]=qf0[v]; g_Qf[n*L+c0+1]=qf1[v];
    }
}

// ---------------- edge aggregation + W2 fold: R9 structure, predicated + unroll for MLP ----------------
__global__ __launch_bounds__(256) void k_aggr(
        const int* __restrict__ colptr, const float4* __restrict__ colE4,
        const int* __restrict__ rowptr, const float4* __restrict__ rowE4,
        const float* __restrict__ Pt, const float* __restrict__ Qt,
        const float* __restrict__ Pf, const float* __restrict__ Qf,
        const float* __restrict__ ptW1, const float* __restrict__ ptb2, const float* __restrict__ ptW2,
        const float* __restrict__ pfW1, const float* __restrict__ pfb2, const float* __restrict__ pfW2,
        float* __restrict__ mt, float* __restrict__ mf){
    bool toDir = (blockIdx.x < NB32);
    int bb = toDir ? blockIdx.x : blockIdx.x - NB32;
    if(bb*32 >= g_ndcount) return;
    __shared__ float sW2[L*L];
    __shared__ float sWe[3*L];
    __shared__ float sS[8][4][L];
    const int*    ptr = toDir ? colptr : rowptr;
    const float4* e4  = toDir ? colE4  : rowE4;
    const float*  P   = toDir ? Pt     : Pf;
    const float*  Q   = toDir ? Qt     : Qf;
    const float*  W1  = toDir ? ptW1   : pfW1;
    const float*  b2  = toDir ? ptb2   : pfb2;
    const float*  W2  = toDir ? ptW2   : pfW2;
    float*        out = toDir ? mt     : mf;
    int tid = threadIdx.x;
    for(int i=tid;i<L*L/4;i+=256) ((float4*)sW2)[i] = ((const float4*)W2)[i];
    for(int i=tid;i<3*L;i+=256) sWe[i] = W1[2*L*L + i];
    __syncthreads();
    int lane = tid&31, w = tid>>5, c0 = 2*lane;
    int sb = bb*32 + w*4;
    float we0a=sWe[c0],     we0b=sWe[c0+1];
    float we1a=sWe[L+c0],   we1b=sWe[L+c0+1];
    float we2a=sWe[2*L+c0], we2b=sWe[2*L+c0+1];
    float degv[4]; bool val[4]; int nid[4];
    #pragma unroll
    for(int v=0;v<4;v++){
        int slot = sb+v;
        val[v] = (slot < g_ndcount);
        int n = val[v]? g_nd[slot] : 0;
        nid[v] = n;
        float acc0=0.f, acc1=0.f; float cnt=0.f;
        if(val[v]){
            float base0 = P[n*L+c0], base1 = P[n*L+c0+1];
            int s = ptr[n], e = ptr[n+1];
            #pragma unroll 4
            for(int p=s; p<e; p++){
                float4 E = e4[p];
                int j = __float_as_int(E.w);
                float2 qv = *(const float2*)&Q[j*L+c0];
                bool keep = (j != n);
                float pre0 = base0 + qv.x + E.x*we0a + E.y*we1a + E.z*we2a;
                float pre1 = base1 + qv.y + E.x*we0b + E.y*we1b + E.z*we2b;
                if(keep){
                    acc0 += fmaxf(pre0, 0.f);
                    acc1 += fmaxf(pre1, 0.f);
                    cnt  += 1.f;
                }
            }
        }
        sS[w][v][c0]=acc0; sS[w][v][c0+1]=acc1; degv[v]=cnt;
    }
    __syncwarp();
    float b2a=b2[c0], b2b=b2[c0+1];
    float o0[4],o1[4];
    #pragma unroll
    for(int v=0;v<4;v++){ o0[v]=degv[v]*b2a; o1[v]=degv[v]*b2b; }
    for(int k=0;k<L;k++){
        float2 wv = *(const float2*)&sW2[k*L+c0];
        #pragma unroll
        for(int v=0;v<4;v++){ float s=sS[w][v][k]; o0[v]=fmaf(s,wv.x,o0[v]); o1[v]=fmaf(s,wv.y,o1[v]); }
    }
    #pragma unroll
    for(int v=0;v<4;v++) if(val[v]){
        int n = nid[v];
        out[n*L+c0]=o0[v]; out[n*L+c0+1]=o1[v];
    }
}

// ---------------- gates: non-dir nodes only, 64/block, 8/warp (R9 version) ----------------
#define GATE_SMEM ((3*194*L + 64*196 + 64*L)*4)
__global__ __launch_bounds__(256) void k_gate(
        const float* __restrict__ prb,
        const float* __restrict__ zkW, const float* __restrict__ zkb,
        const float* __restrict__ rkW, const float* __restrict__ rkb,
        const float* __restrict__ cW,  const float* __restrict__ cb){
    if(blockIdx.x*64 >= g_ndcount) return;
    extern __shared__ float sm[];
    float* szk  = sm;
    float* srk  = szk + 194*L;
    float* scw  = srk + 194*L;
    float* stgA = scw + 194*L;        // [64][196]
    float* stgB = stgA + 64*196;      // [64][64]
    __shared__ float szb[L], srb[L], scb[L];
    int tid = threadIdx.x;
    for(int i=tid;i<194*L/4;i+=256){
        ((float4*)szk)[i] = ((const float4*)zkW)[i];
        ((float4*)srk)[i] = ((const float4*)rkW)[i];
        ((float4*)scw)[i] = ((const float4*)cW)[i];
    }
    if(tid<L){ szb[tid]=zkb[tid]; srb[tid]=rkb[tid]; scb[tid]=cb[tid]; }
    int lane = tid&31, w = tid>>5, c0 = 2*lane;
    int i0 = w*8, sb = blockIdx.x*64 + i0;
    int nid[8]; bool val[8];
    #pragma unroll
    for(int v=0;v<8;v++){
        int slot = sb+v; val[v] = (slot < g_ndcount);
        int n = val[v]? g_nd[slot] : 0; nid[v] = n;
        float* A = stgA + (i0+v)*196;
        if(val[v]){
            *(float2*)&A[c0]     = *(const float2*)&g_H [n*L+c0];
            *(float2*)&A[64+c0]  = *(const float2*)&g_mt[n*L+c0];
            *(float2*)&A[128+c0] = *(const float2*)&g_mf[n*L+c0];
            if(lane==0){ A[192]=prb[2*n]; A[193]=prb[2*n+1]; }
        } else {
            *(float2*)&A[c0]     = make_float2(0.f,0.f);
            *(float2*)&A[64+c0]  = make_float2(0.f,0.f);
            *(float2*)&A[128+c0] = make_float2(0.f,0.f);
            if(lane==0){ A[192]=0.f; A[193]=0.f; }
        }
    }
    __syncthreads();
    float az0[8],az1[8],ar0[8],ar1[8],ac0[8],ac1[8];
    #pragma unroll
    for(int v=0;v<8;v++){ az0[v]=0.f; az1[v]=0.f; ar0[v]=0.f; ar1[v]=0.f; ac0[v]=0.f; ac1[v]=0.f; }
    for(int k=0;k<64;k++){
        float2 wz = *(const float2*)&szk[k*L+c0];
        float2 wr = *(const float2*)&srk[k*L+c0];
        #pragma unroll
        for(int v=0;v<8;v++){
            float cv = stgA[(i0+v)*196 + k];
            az0[v]=fmaf(cv,wz.x,az0[v]); az1[v]=fmaf(cv,wz.y,az1[v]);
            ar0[v]=fmaf(cv,wr.x,ar0[v]); ar1[v]=fmaf(cv,wr.y,ar1[v]);
        }
    }
    for(int k=64;k<194;k++){
        float2 wz = *(const float2*)&szk[k*L+c0];
        float2 wr = *(const float2*)&srk[k*L+c0];
        float2 wc = *(const float2*)&scw[k*L+c0];
        #pragma unroll
        for(int v=0;v<8;v++){
            float cv = stgA[(i0+v)*196 + k];
            az0[v]=fmaf(cv,wz.x,az0[v]); az1[v]=fmaf(cv,wz.y,az1[v]);
            ar0[v]=fmaf(cv,wr.x,ar0[v]); ar1[v]=fmaf(cv,wr.y,ar1[v]);
            ac0[v]=fmaf(cv,wc.x,ac0[v]); ac1[v]=fmaf(cv,wc.y,ac1[v]);
        }
    }
    float z0[8],z1[8];
    #pragma unroll
    for(int v=0;v<8;v++){
        z0[v]=sigf(az0[v]+szb[c0]); z1[v]=sigf(az1[v]+szb[c0+1]);
        float rr0=sigf(ar0[v]+srb[c0]), rr1=sigf(ar1[v]+srb[c0+1]);
        stgB[(i0+v)*L+c0]=rr0; stgB[(i0+v)*L+c0+1]=rr1;
    }
    __syncwarp();
    for(int k=0;k<64;k++){
        float2 wc = *(const float2*)&scw[k*L+c0];
        #pragma unroll
        for(int v=0;v<8;v++){
            float rh = stgB[(i0+v)*L+k] * stgA[(i0+v)*196+k];
            ac0[v]=fmaf(rh,wc.x,ac0[v]); ac1[v]=fmaf(rh,wc.y,ac1[v]);
        }
    }
    #pragma unroll
    for(int v=0;v<8;v++) if(val[v]){
        int n = nid[v];
        float* A = stgA + (i0+v)*196;
        float co0 = tanhf(ac0[v]+scb[c0]);
        float co1 = tanhf(ac1[v]+scb[c0+1]);
        float hn0 = A[c0]   + z0[v]*co0;
        float hn1 = A[c0+1] + z1[v]*co1;
        g_H[n*L+c0]   = hn0;
        g_H[n*L+c0+1] = hn1;
    }
}

// ---------------- decode + enc/autoenc losses over a node list (R9 version) ----------------
#define DEC_SMEM (3*64*L*4)
__global__ __launch_bounds__(256) void k_decode(
        int mode, float lossW,
        const float* __restrict__ dW1, const float* __restrict__ db1,
        const float* __restrict__ dW2, const float* __restrict__ db2,
        const float* __restrict__ eW1, const float* __restrict__ eb1,
        const float* __restrict__ eW2, const float* __restrict__ eb2){
    int cnt = mode ? g_ndcount : g_drcount;
    if(blockIdx.x*64 >= cnt) return;
    const int* list = mode ? g_nd : g_dr;
    extern __shared__ float sm[];
    float* sHn = sm;
    float* sB  = sm + 64*L;
    float* sE  = sm + 2*64*L;
    __shared__ float sdW2[L], sdb1[L], sE1[L], sEb1[L], sEb2[L];
    __shared__ double red[8];
    int tid = threadIdx.x;
    if(tid<L){ sdW2[tid]=dW2[tid]; sdb1[tid]=db1[tid]; sE1[tid]=eW1[tid];
               sEb1[tid]=eb1[tid]; sEb2[tid]=eb2[tid]; }
    __syncthreads();
    int lane = tid&31, w = tid>>5, c0 = 2*lane;
    int i0 = w*8, sb = blockIdx.x*64 + i0;
    float db2v = db2[0];
    int nid[8]; bool val[8];
    #pragma unroll
    for(int v=0;v<8;v++){
        int slot = sb+v; val[v] = (slot < cnt);
        nid[v] = val[v]? list[slot] : 0;
        float2 h = val[v]? *(const float2*)&g_H[nid[v]*L+c0] : make_float2(0.f,0.f);
        *(float2*)&sHn[(i0+v)*L+c0] = h;
    }
    __syncwarp();
    float ad0[8],ad1[8];
    #pragma unroll
    for(int v=0;v<8;v++){ ad0[v]=sdb1[c0]; ad1[v]=sdb1[c0+1]; }
    for(int k=0;k<L;k++){
        float2 wd = __ldg((const float2*)&dW1[k*L+c0]);
        #pragma unroll
        for(int v=0;v<8;v++){
            float hk = sHn[(i0+v)*L+k];
            ad0[v]=fmaf(hk,wd.x,ad0[v]); ad1[v]=fmaf(hk,wd.y,ad1[v]);
        }
    }
    float Uv[8];
    #pragma unroll
    for(int v=0;v<8;v++){
        float pu = fmaxf(ad0[v],0.f)*sdW2[c0] + fmaxf(ad1[v],0.f)*sdW2[c0+1];
        for(int o=16;o;o>>=1) pu += __shfl_xor_sync(0xffffffffu, pu, o);
        Uv[v] = pu + db2v;
        if(val[v] && lane==0) g_U[nid[v]] = Uv[v];
        float eh0 = fmaxf(fmaf(Uv[v],sE1[c0],sEb1[c0]),0.f);
        float eh1 = fmaxf(fmaf(Uv[v],sE1[c0+1],sEb1[c0+1]),0.f);
        sB[(i0+v)*L+c0]=eh0; sB[(i0+v)*L+c0+1]=eh1;
    }
    __syncwarp();
    float ae0[8],ae1[8];
    #pragma unroll
    for(int v=0;v<8;v++){ ae0[v]=sEb2[c0]; ae1[v]=sEb2[c0+1]; }
    for(int k=0;k<L;k++){
        float2 we = __ldg((const float2*)&eW2[k*L+c0]);
        #pragma unroll
        for(int v=0;v<8;v++){
            float ek = sB[(i0+v)*L+k];
            ae0[v]=fmaf(ek,we.x,ae0[v]); ae1[v]=fmaf(ek,we.y,ae1[v]);
        }
    }
    float encS = 0.f;
    #pragma unroll
    for(int v=0;v<8;v++){
        if(val[v]){
            float d0 = ae0[v]-sHn[(i0+v)*L+c0], d1 = ae1[v]-sHn[(i0+v)*L+c0+1];
            encS += d0*d0 + d1*d1;
        }
        sE[(i0+v)*L+c0]=ae0[v]; sE[(i0+v)*L+c0+1]=ae1[v];
    }
    __syncwarp();
    float ag0[8],ag1[8];
    #pragma unroll
    for(int v=0;v<8;v++){ ag0[v]=sdb1[c0]; ag1[v]=sdb1[c0+1]; }
    for(int k=0;k<L;k++){
        float2 wd = __ldg((const float2*)&dW1[k*L+c0]);
        #pragma unroll
        for(int v=0;v<8;v++){
            float ek = sE[(i0+v)*L+k];
            ag0[v]=fmaf(ek,wd.x,ag0[v]); ag1[v]=fmaf(ek,wd.y,ag1[v]);
        }
    }
    float autoS = 0.f;
    #pragma unroll
    for(int v=0;v<8;v++){
        float pa = fmaxf(ag0[v],0.f)*sdW2[c0] + fmaxf(ag1[v],0.f)*sdW2[c0+1];
        for(int o=16;o;o>>=1) pa += __shfl_xor_sync(0xffffffffu, pa, o);
        float aout = pa + db2v;
        if(val[v] && lane==0){ float d = aout - Uv[v]; autoS += d*d; }
    }
    float tot = encS;
    for(int o=16;o;o>>=1) tot += __shfl_xor_sync(0xffffffffu, tot, o);
    float at = autoS;
    for(int o=16;o;o>>=1) at += __shfl_xor_sync(0xffffffffu, at, o);
    if(lane==0) red[w] = (double)lossW * ((double)tot/((double)NN*64.0) + (double)at/(double)NN);
    __syncthreads();
    if(tid==0){
        double s = 0.0;
        for(int i=0;i<8;i++) s += red[i];
        atomicAdd(&g_loss, s);
    }
}

// ---------------- residual loss (rowJ/rowA: 8B/edge) ----------------
__global__ __launch_bounds__(256) void k_res(const float* __restrict__ y, float wgt){
    __shared__ double red[8];
    int lane = threadIdx.x&31, w = threadIdx.x>>5;
    int wid = blockIdx.x*8 + w;
    int nwarps = gridDim.x*8;
    float ls = 0.f;
    for(int n = wid; n < NN; n += nwarps){
        int s = g_rowptr[n], e = g_rowptr[n+1];
        float part = 0.f;
        for(int p = s+lane; p < e; p += 32){
            part += g_rowA[p] * g_U[g_rowJ[p]];
        }
        for(int o=16;o;o>>=1) part += __shfl_xor_sync(0xffffffffu, part, o);
        if(lane==0){ float d = part - y[n]; ls += d*d; }
    }
    for(int o=16;o;o>>=1) ls += __shfl_xor_sync(0xffffffffu, ls, o);
    if(lane==0) red[w] = (double)ls;
    __syncthreads();
    if(threadIdx.x==0){
        double s=0.0; for(int i=0;i<8;i++) s+=red[i];
        atomicAdd(&g_loss, s * (double)wgt / (double)NN);
    }
}

// ---------------- finalize + reset state for next replay ----------------
__global__ void k_fin(float* __restrict__ out, int out_size){
    int i = blockIdx.x*blockDim.x + threadIdx.x;
    if(i < NN && i < out_size) out[i] = g_U[i];
    if(i == NN){
        if(i < out_size) out[NN] = (float)g_loss;
        g_loss = 0.0;
    }
    if(i < NN){ g_cntr[i]=0; g_cntc[i]=0; }
}

extern "C" void kernel_launch(void* const* d_in, const int* in_sizes, int n_in,
                              void* d_out, int out_size){
    const float* x    = (const float*)d_in[0];
    const float* y    = (const float*)d_in[2];
    const int*   tags = (const int*)  d_in[3];
    const int*   ei   = (const int*)  d_in[4];
    const float* ea   = (const float*)d_in[5];
    const float* aij  = (const float*)d_in[6];
    const float* prb  = (const float*)d_in[7];
    const float* ptW1 = (const float*)d_in[8];
    const float* ptb1 = (const float*)d_in[9];
    const float* ptW2 = (const float*)d_in[10];
    const float* ptb2 = (const float*)d_in[11];
    const float* pfW1 = (const float*)d_in[12];
    const float* pfb1 = (const float*)d_in[13];
    const float* pfW2 = (const float*)d_in[14];
    const float* pfb2 = (const float*)d_in[15];
    const float* zkW  = (const float*)d_in[16];
    const float* zkb  = (const float*)d_in[17];
    const float* rkW  = (const float*)d_in[18];
    const float* rkb  = (const float*)d_in[19];
    const float* cW   = (const float*)d_in[20];
    const float* cb   = (const float*)d_in[21];
    const float* eW1  = (const float*)d_in[22];
    const float* eb1  = (const float*)d_in[23];
    const float* eW2  = (const float*)d_in[24];
    const float* eb2  = (const float*)d_in[25];
    const float* dW1  = (const float*)d_in[26];
    const float* db1  = (const float*)d_in[27];
    const float* dW2  = (const float*)d_in[28];
    const float* db2  = (const float*)d_in[29];

    cudaFuncSetAttribute(k_prep,   cudaFuncAttributeMaxDynamicSharedMemorySize, PREP_SMEM);
    cudaFuncSetAttribute(k_gate,   cudaFuncAttributeMaxDynamicSharedMemorySize, GATE_SMEM);
    cudaFuncSetAttribute(k_decode, cudaFuncAttributeMaxDynamicSharedMemorySize, DEC_SMEM);

    int *rowptr, *colptr;
    float4 *rowE4, *colE4;
    float *Pt, *Qt, *Pf, *Qf, *mt, *mf;
    cudaGetSymbolAddress((void**)&rowptr, g_rowptr);
    cudaGetSymbolAddress((void**)&colptr, g_colptr);
    cudaGetSymbolAddress((void**)&rowE4,  g_rowE4);
    cudaGetSymbolAddress((void**)&colE4,  g_colE4);
    cudaGetSymbolAddress((void**)&Pt, g_Pt);
    cudaGetSymbolAddress((void**)&Qt, g_Qt);
    cudaGetSymbolAddress((void**)&Pf, g_Pf);
    cudaGetSymbolAddress((void**)&Qf, g_Qf);
    cudaGetSymbolAddress((void**)&mt, g_mt);
    cudaGetSymbolAddress((void**)&mf, g_mf);

    k_enc0<<<NB32, 256>>>(x, eW1, eb1, eW2, eb2);                        // 0
    k_hist<<<(NE+255)/256, 256>>>(ei);                                   // 1
    k_scan<<<1, 1024>>>(tags);                                           // 2
    k_prep<<<NB64, 256, PREP_SMEM>>>(ptW1, ptb1, pfW1, pfb1, 0);         // 3 (profiled control)
    k_scatter<<<(NE+255)/256, 256>>>(ei, ea, aij);                       // 4
    // Dirichlet nodes: losses identical both steps -> once, weight 2
    k_decode<<<NB64, 256, DEC_SMEM>>>(0, 2.0f, dW1, db1, dW2, db2, eW1, eb1, eW2, eb2);

    const float gammaw[2] = {0.9f, 1.0f};
    for(int step=0; step<2; step++){
        k_aggr<<<2*NB32, 256>>>(colptr, colE4, rowptr, rowE4,
                                Pt, Qt, Pf, Qf,
                                ptW1, ptb2, ptW2, pfW1, pfb2, pfW2, mt, mf);
        k_gate<<<NB64, 256, GATE_SMEM>>>(prb, zkW, zkb, rkW, rkb, cW, cb);
        k_decode<<<NB64, 256, DEC_SMEM>>>(1, 1.0f, dW1, db1, dW2, db2, eW1, eb1, eW2, eb2);
        k_res<<<NB32, 256>>>(y, gammaw[step]);
        if(step == 0)
            k_prep<<<NB64, 256, PREP_SMEM>>>(ptW1, ptb1, pfW1, pfb1, 1);
    }
    k_fin<<<(NN+256)/256, 256>>>((float*)d_out, out_size);
}